// round 2
// baseline (speedup 1.0000x reference)
#include <cuda_runtime.h>
#include <cstdint>
#include <cstddef>

// Problem dims (fixed by the dataset)
#define SDIM 256          // n_seq (attention/key axis)
#define LDIM 192          // n_res
#define DDIM 256          // model dim
#define HN   8            // heads
#define CN   32           // head dim
#define NROWS (LDIM*SDIM) // 49152 rows of the (L,S) grid
#define SEG  ((size_t)NROWS*DDIM)   // 12,582,912 elements per projection segment

// -------- scratch (device globals; no allocation in kernel_launch) --------
__device__ float g_XN[(size_t)NROWS*DDIM];       // layernormed x, [L][S][D]
__device__ float g_P[(size_t)4*NROWS*DDIM];      // q,k,v,g each [L][H][S][C]
__device__ float g_CTX[(size_t)NROWS*DDIM];      // gated context, [L][S][D]
__device__ float g_bias[LDIM*SDIM];              // pad bias [L][S] (0 or -10000)

// ============================================================
// Pad-mask kernel with runtime dtype classification for bool inputs.
// Word mode: every 4-byte word is 0 / 1 (int32) or 0 / 0x3F800000 (float32)
//   -> in both cases "word != 0" gives the flag.
// Byte mode (uint8/bool): read bytes.
// ============================================================
__device__ __forceinline__ int classify_words(const int* w, int nwords) {
    int wordlike = 1;
    for (int i = 0; i < nwords; i++) {
        int v = w[i];
        if (v != 0 && v != 1 && v != 0x3F800000) wordlike = 0;
    }
    return wordlike;   // 1 => 4-byte elements, 0 => 1-byte elements
}

__global__ void mask_kernel(const void* __restrict__ seqp,
                            const void* __restrict__ resp) {
    __shared__ int s_seqw, s_resw;
    if (threadIdx.x == 0) {
        // seq_pad: 256 elems -> 64 words safe either way (256 bytes min)
        s_seqw = classify_words((const int*)seqp, 64);
        // res_pad: 192 elems -> 48 words safe either way (192 bytes min)
        s_resw = classify_words((const int*)resp, 48);
    }
    __syncthreads();
    const int seqw = s_seqw, resw = s_resw;
    for (int idx = threadIdx.x; idx < LDIM * SDIM; idx += blockDim.x) {
        int l = idx >> 8;        // / 256
        int t = idx & 255;
        int rp = resw ? (((const int*)resp)[l] != 0)
                      : (((const unsigned char*)resp)[l] != 0);
        int sp = seqw ? (((const int*)seqp)[t] != 0)
                      : (((const unsigned char*)seqp)[t] != 0);
        g_bias[idx] = (rp | sp) ? -10000.0f : 0.0f;
    }
}

// ============================================================
// LayerNorm: one block per (l,s) row; reads m[s][l][:] (transpose on the fly)
// ============================================================
__global__ __launch_bounds__(256) void ln_kernel(const float* __restrict__ m,
                                                 const float* __restrict__ scale,
                                                 const float* __restrict__ bias) {
    int r = blockIdx.x;          // r = l*256 + s
    int l = r >> 8;
    int s = r & 255;
    int d = threadIdx.x;
    float v = m[((size_t)(s * LDIM + l)) * DDIM + d];

    float sum = v, sq = v * v;
    #pragma unroll
    for (int o = 16; o > 0; o >>= 1) {
        sum += __shfl_xor_sync(0xFFFFFFFFu, sum, o);
        sq  += __shfl_xor_sync(0xFFFFFFFFu, sq, o);
    }
    __shared__ float ssum[8], ssq[8];
    int w = threadIdx.x >> 5, ln = threadIdx.x & 31;
    if (ln == 0) { ssum[w] = sum; ssq[w] = sq; }
    __syncthreads();
    if (w == 0) {
        float a = (ln < 8) ? ssum[ln] : 0.f;
        float b = (ln < 8) ? ssq[ln]  : 0.f;
        #pragma unroll
        for (int o = 4; o > 0; o >>= 1) {
            a += __shfl_xor_sync(0xFFFFFFFFu, a, o);
            b += __shfl_xor_sync(0xFFFFFFFFu, b, o);
        }
        if (ln == 0) { ssum[0] = a; ssq[0] = b; }
    }
    __syncthreads();
    float mu   = ssum[0] * (1.0f / DDIM);
    float var  = ssq[0] * (1.0f / DDIM) - mu * mu;
    float rstd = rsqrtf(var + 1e-5f);
    g_XN[(size_t)r * DDIM + d] = (v - mu) * rstd * scale[d] + bias[d];
}

// ============================================================
// Projection GEMM: P[r][n] = sum_d XN[r][d] * W[n][d] for W in {wq,wk,wv,wg}
// BM=BN=64, BK=16, 256 threads, 4x4 micro-tile, both tiles k-major in smem.
// Epilogue: q scaled by 1/sqrt(C); g = sigmoid(.+bg); write [L][H][S][C].
// ============================================================
__global__ __launch_bounds__(256, 2) void proj_kernel(
    const float* __restrict__ wq, const float* __restrict__ wk,
    const float* __restrict__ wv, const float* __restrict__ wg,
    const float* __restrict__ bgv) {
    __shared__ float Ast[16][68];   // [k][m], padded
    __shared__ float Bst[16][68];   // [k][n], padded

    int tid = threadIdx.x;
    int tx = tid & 15, ty = tid >> 4;
    int arow = tid >> 2, aq = tid & 3;

    int r0  = blockIdx.x << 6;
    int mat = blockIdx.y >> 2;                 // 0=q,1=k,2=v,3=g
    int n0  = (blockIdx.y & 3) << 6;
    const float* W = (mat == 0) ? wq : (mat == 1) ? wk : (mat == 2) ? wv : wg;

    float acc[4][4] = {};
    const float* Aptr = g_XN + (size_t)(r0 + arow) * DDIM + aq * 4;
    const float* Bptr = W    + (size_t)(n0 + arow) * DDIM + aq * 4;

    for (int k0 = 0; k0 < DDIM; k0 += 16) {
        float4 av = *(const float4*)(Aptr + k0);
        float4 bv = *(const float4*)(Bptr + k0);
        __syncthreads();
        int kq = aq * 4;
        Ast[kq + 0][arow] = av.x; Ast[kq + 1][arow] = av.y;
        Ast[kq + 2][arow] = av.z; Ast[kq + 3][arow] = av.w;
        Bst[kq + 0][arow] = bv.x; Bst[kq + 1][arow] = bv.y;
        Bst[kq + 2][arow] = bv.z; Bst[kq + 3][arow] = bv.w;
        __syncthreads();
        #pragma unroll
        for (int k = 0; k < 16; k++) {
            float4 a4 = *(const float4*)&Ast[k][ty << 2];
            float4 b4 = *(const float4*)&Bst[k][tx << 2];
            float a[4] = {a4.x, a4.y, a4.z, a4.w};
            float b[4] = {b4.x, b4.y, b4.z, b4.w};
            #pragma unroll
            for (int i = 0; i < 4; i++)
                #pragma unroll
                for (int j = 0; j < 4; j++)
                    acc[i][j] += a[i] * b[j];
        }
    }

    int nb = n0 + (tx << 2);       // 4 consecutive cols, same head
    int h  = nb >> 5;
    int c0 = nb & 31;
    #pragma unroll
    for (int i = 0; i < 4; i++) {
        int r = r0 + (ty << 2) + i;
        int l = r >> 8, s = r & 255;
        float o[4];
        #pragma unroll
        for (int j = 0; j < 4; j++) {
            float v = acc[i][j];
            if (mat == 0)      v *= 0.17677669529663687f;            // 1/sqrt(32)
            else if (mat == 3) v = 1.0f / (1.0f + __expf(-(v + bgv[nb + j])));
            o[j] = v;
        }
        float* dst = g_P + (size_t)mat * SEG
                   + ((size_t)((l * HN + h) * SDIM + s)) * CN + c0;
        *(float4*)dst = make_float4(o[0], o[1], o[2], o[3]);
    }
}

// ============================================================
// Attention: one block per (l,h). 256 threads = 1 thread per query.
// K,V (8192 floats each) + bias row in dynamic smem (65 KB).
// Pass 1: logits -> local array + running max.
// Pass 2: e=exp(logit-max); sum+=e; ctx += e*V (unnormalized).
// Final: ctx *= g * (1/sum); write [L][S][D].
// ============================================================
__global__ __launch_bounds__(256) void attn_kernel() {
    extern __shared__ float sm[];
    float* Ks = sm;
    float* Vs = sm + SDIM * CN;
    float* Bb = sm + 2 * SDIM * CN;

    int lh = blockIdx.x;
    int l = lh >> 3;
    size_t base = (size_t)lh * SDIM * CN;      // (l*H+h)*S*C

    const float4* Kg = (const float4*)(g_P + SEG + base);
    const float4* Vg = (const float4*)(g_P + 2 * SEG + base);
    float4* Ks4 = (float4*)Ks;
    float4* Vs4 = (float4*)Vs;
    int tid = threadIdx.x;
    #pragma unroll
    for (int i = 0; i < 8; i++) {
        Ks4[tid + 256 * i] = Kg[tid + 256 * i];
        Vs4[tid + 256 * i] = Vg[tid + 256 * i];
    }
    Bb[tid] = g_bias[l * SDIM + tid];
    __syncthreads();

    float q[32];
    const float4* Qg = (const float4*)(g_P + base + (size_t)tid * CN);
    #pragma unroll
    for (int c = 0; c < 8; c++) {
        float4 t4 = Qg[c];
        q[4*c] = t4.x; q[4*c+1] = t4.y; q[4*c+2] = t4.z; q[4*c+3] = t4.w;
    }

    float larr[SDIM];
    float mx = -3.0e38f;
    for (int t = 0; t < SDIM; t++) {
        const float4* kr = (const float4*)(Ks + t * CN);
        float d0 = 0, d1 = 0, d2 = 0, d3 = 0;
        #pragma unroll
        for (int c = 0; c < 8; c++) {
            float4 k4 = kr[c];
            d0 += q[4*c]   * k4.x;
            d1 += q[4*c+1] * k4.y;
            d2 += q[4*c+2] * k4.z;
            d3 += q[4*c+3] * k4.w;
        }
        float dd = (d0 + d1) + (d2 + d3) + Bb[t];
        larr[t] = dd;
        mx = fmaxf(mx, dd);
    }

    float sum = 0.0f;
    float ctx[32];
    #pragma unroll
    for (int c = 0; c < 32; c++) ctx[c] = 0.0f;
    for (int t = 0; t < SDIM; t++) {
        float e = __expf(larr[t] - mx);
        sum += e;
        const float4* vr = (const float4*)(Vs + t * CN);
        #pragma unroll
        for (int c = 0; c < 8; c++) {
            float4 v4 = vr[c];
            ctx[4*c]   += e * v4.x;
            ctx[4*c+1] += e * v4.y;
            ctx[4*c+2] += e * v4.z;
            ctx[4*c+3] += e * v4.w;
        }
    }
    float inv = 1.0f / sum;

    const float4* Gg = (const float4*)(g_P + 3 * SEG + base + (size_t)tid * CN);
    int h = lh & 7;
    float4* Co = (float4*)(g_CTX + ((size_t)(l * SDIM + tid)) * DDIM + h * CN);
    #pragma unroll
    for (int c = 0; c < 8; c++) {
        float4 g4 = Gg[c];
        float4 o;
        o.x = ctx[4*c]   * inv * g4.x;
        o.y = ctx[4*c+1] * inv * g4.y;
        o.z = ctx[4*c+2] * inv * g4.z;
        o.w = ctx[4*c+3] * inv * g4.w;
        Co[c] = o;
    }
}

// ============================================================
// Output GEMM: out[s][l][n] = sum_d CTX[l*S+s][d] * wo[n][d] + bo[n]
// ============================================================
__global__ __launch_bounds__(256, 2) void out_kernel(
    const float* __restrict__ wo, const float* __restrict__ bo,
    float* __restrict__ out) {
    __shared__ float Ast[16][68];
    __shared__ float Bst[16][68];

    int tid = threadIdx.x;
    int tx = tid & 15, ty = tid >> 4;
    int arow = tid >> 2, aq = tid & 3;

    int r0 = blockIdx.x << 6;
    int n0 = blockIdx.y << 6;

    float acc[4][4] = {};
    const float* Aptr = g_CTX + (size_t)(r0 + arow) * DDIM + aq * 4;
    const float* Bptr = wo    + (size_t)(n0 + arow) * DDIM + aq * 4;

    for (int k0 = 0; k0 < DDIM; k0 += 16) {
        float4 av = *(const float4*)(Aptr + k0);
        float4 bv = *(const float4*)(Bptr + k0);
        __syncthreads();
        int kq = aq * 4;
        Ast[kq + 0][arow] = av.x; Ast[kq + 1][arow] = av.y;
        Ast[kq + 2][arow] = av.z; Ast[kq + 3][arow] = av.w;
        Bst[kq + 0][arow] = bv.x; Bst[kq + 1][arow] = bv.y;
        Bst[kq + 2][arow] = bv.z; Bst[kq + 3][arow] = bv.w;
        __syncthreads();
        #pragma unroll
        for (int k = 0; k < 16; k++) {
            float4 a4 = *(const float4*)&Ast[k][ty << 2];
            float4 b4 = *(const float4*)&Bst[k][tx << 2];
            float a[4] = {a4.x, a4.y, a4.z, a4.w};
            float b[4] = {b4.x, b4.y, b4.z, b4.w};
            #pragma unroll
            for (int i = 0; i < 4; i++)
                #pragma unroll
                for (int j = 0; j < 4; j++)
                    acc[i][j] += a[i] * b[j];
        }
    }

    int nb = n0 + (tx << 2);
    #pragma unroll
    for (int i = 0; i < 4; i++) {
        int r = r0 + (ty << 2) + i;
        int l = r >> 8, s = r & 255;
        float4 o;
        o.x = acc[i][0] + bo[nb + 0];
        o.y = acc[i][1] + bo[nb + 1];
        o.z = acc[i][2] + bo[nb + 2];
        o.w = acc[i][3] + bo[nb + 3];
        *(float4*)(out + (size_t)(s * LDIM + l) * DDIM + nb) = o;
    }
}

// ============================================================
extern "C" void kernel_launch(void* const* d_in, const int* in_sizes, int n_in,
                              void* d_out, int out_size) {
    const float* m        = (const float*)d_in[0];
    const void*  seqp     = d_in[1];
    const void*  resp     = d_in[2];
    const float* ln_scale = (const float*)d_in[3];
    const float* ln_bias  = (const float*)d_in[4];
    const float* wq       = (const float*)d_in[5];
    const float* wk       = (const float*)d_in[6];
    const float* wv       = (const float*)d_in[7];
    const float* wg       = (const float*)d_in[8];
    const float* bg       = (const float*)d_in[9];
    const float* wo       = (const float*)d_in[10];
    const float* bo       = (const float*)d_in[11];
    float* out = (float*)d_out;

    const int attn_smem = (2 * SDIM * CN + SDIM) * (int)sizeof(float); // 66560 B
    cudaFuncSetAttribute(attn_kernel,
                         cudaFuncAttributeMaxDynamicSharedMemorySize, attn_smem);

    mask_kernel<<<1, 256>>>(seqp, resp);
    ln_kernel<<<NROWS, 256>>>(m, ln_scale, ln_bias);
    proj_kernel<<<dim3(NROWS / 64, 16), 256>>>(wq, wk, wv, wg, bg);
    attn_kernel<<<LDIM * HN, 256, attn_smem>>>();
    out_kernel<<<dim3(NROWS / 64, 4), 256>>>(wo, bo, out);
}

// round 3
// speedup vs baseline: 2.5362x; 2.5362x over previous
#include <cuda_runtime.h>
#include <cstdint>
#include <cstddef>

#define SDIM 256
#define LDIM 192
#define DDIM 256
#define HN   8
#define CN   32
#define NROWS (LDIM*SDIM)
#define SEG  ((size_t)NROWS*DDIM)

__device__ float g_XN[(size_t)NROWS*DDIM];
__device__ float g_P[(size_t)4*NROWS*DDIM];
__device__ float g_CTX[(size_t)NROWS*DDIM];
__device__ float g_bias[LDIM*SDIM];

// ---------- tf32 mma helpers ----------
__device__ __forceinline__ unsigned f2tf(float f) {
    unsigned u;
    asm("cvt.rna.tf32.f32 %0, %1;" : "=r"(u) : "f"(f));
    return u;
}
__device__ __forceinline__ void mma_tf32(float* d, const unsigned* a,
                                         const unsigned* b, const float* c) {
    asm("mma.sync.aligned.m16n8k8.row.col.f32.tf32.tf32.f32 "
        "{%0,%1,%2,%3}, {%4,%5,%6,%7}, {%8,%9}, {%10,%11,%12,%13};"
        : "=f"(d[0]), "=f"(d[1]), "=f"(d[2]), "=f"(d[3])
        : "r"(a[0]), "r"(a[1]), "r"(a[2]), "r"(a[3]),
          "r"(b[0]), "r"(b[1]),
          "f"(c[0]), "f"(c[1]), "f"(c[2]), "f"(c[3]));
}

// ============================================================
// Pad mask (runtime dtype classification for bool inputs)
// ============================================================
__device__ __forceinline__ int classify_words(const int* w, int nwords) {
    int wordlike = 1;
    for (int i = 0; i < nwords; i++) {
        int v = w[i];
        if (v != 0 && v != 1 && v != 0x3F800000) wordlike = 0;
    }
    return wordlike;
}

__global__ void mask_kernel(const void* __restrict__ seqp,
                            const void* __restrict__ resp) {
    __shared__ int s_seqw, s_resw;
    if (threadIdx.x == 0) {
        s_seqw = classify_words((const int*)seqp, 64);
        s_resw = classify_words((const int*)resp, 48);
    }
    __syncthreads();
    const int seqw = s_seqw, resw = s_resw;
    int idx = blockIdx.x * 256 + threadIdx.x;
    int l = idx >> 8;
    int t = idx & 255;
    int rp = resw ? (((const int*)resp)[l] != 0)
                  : (((const unsigned char*)resp)[l] != 0);
    int sp = seqw ? (((const int*)seqp)[t] != 0)
                  : (((const unsigned char*)seqp)[t] != 0);
    g_bias[idx] = (rp | sp) ? -10000.0f : 0.0f;
}

// ============================================================
// LayerNorm (transpose on the fly)
// ============================================================
__global__ __launch_bounds__(256) void ln_kernel(const float* __restrict__ m,
                                                 const float* __restrict__ scale,
                                                 const float* __restrict__ bias) {
    int r = blockIdx.x;
    int l = r >> 8;
    int s = r & 255;
    int d = threadIdx.x;
    float v = m[((size_t)(s * LDIM + l)) * DDIM + d];

    float sum = v, sq = v * v;
    #pragma unroll
    for (int o = 16; o > 0; o >>= 1) {
        sum += __shfl_xor_sync(0xFFFFFFFFu, sum, o);
        sq  += __shfl_xor_sync(0xFFFFFFFFu, sq, o);
    }
    __shared__ float ssum[8], ssq[8];
    int w = threadIdx.x >> 5, ln = threadIdx.x & 31;
    if (ln == 0) { ssum[w] = sum; ssq[w] = sq; }
    __syncthreads();
    if (w == 0) {
        float a = (ln < 8) ? ssum[ln] : 0.f;
        float b = (ln < 8) ? ssq[ln]  : 0.f;
        #pragma unroll
        for (int o = 4; o > 0; o >>= 1) {
            a += __shfl_xor_sync(0xFFFFFFFFu, a, o);
            b += __shfl_xor_sync(0xFFFFFFFFu, b, o);
        }
        if (ln == 0) { ssum[0] = a; ssq[0] = b; }
    }
    __syncthreads();
    float mu   = ssum[0] * (1.0f / DDIM);
    float var  = ssq[0] * (1.0f / DDIM) - mu * mu;
    float rstd = rsqrtf(var + 1e-5f);
    g_XN[(size_t)r * DDIM + d] = (v - mu) * rstd * scale[d] + bias[d];
}

// ============================================================
// Projection GEMM (tf32 mma): block 128x128, 8 warps (4m x 2n),
// warp 32x64 = 2 m-tiles x 8 n-tiles. K tiles of 32.
// ============================================================
__global__ __launch_bounds__(256, 2) void proj_mma_kernel(
    const float* __restrict__ wq, const float* __restrict__ wk,
    const float* __restrict__ wv, const float* __restrict__ wg,
    const float* __restrict__ bgv) {
    __shared__ float As[128 * 36];
    __shared__ float Bs[128 * 36];

    int tid = threadIdx.x, warp = tid >> 5, lane = tid & 31;
    int lr = lane >> 2, lc4 = lane & 3;
    int wm = (warp >> 1) << 5;   // 0,32,64,96
    int wn = (warp & 1) << 6;    // 0,64

    int r0  = blockIdx.x << 7;
    int mat = blockIdx.y >> 1;
    int n0  = (blockIdx.y & 1) << 7;
    const float* W = (mat == 0) ? wq : (mat == 1) ? wk : (mat == 2) ? wv : wg;
    const float* Ag = g_XN;

    float acc[16][4] = {};

    for (int k0 = 0; k0 < 256; k0 += 32) {
        #pragma unroll
        for (int i = 0; i < 4; i++) {
            int idx = tid + (i << 8);
            int row = idx >> 3, c4 = (idx & 7) << 2;
            float4 v = *(const float4*)(Ag + (size_t)(r0 + row) * 256 + k0 + c4);
            *(float4*)&As[row * 36 + c4] = v;
            float4 b = *(const float4*)(W + (size_t)(n0 + row) * 256 + k0 + c4);
            *(float4*)&Bs[row * 36 + c4] = b;
        }
        __syncthreads();
        #pragma unroll
        for (int ks = 0; ks < 32; ks += 8) {
            unsigned af[2][4], bf[8][2];
            #pragma unroll
            for (int mt = 0; mt < 2; mt++) {
                int r = wm + mt * 16 + lr;
                af[mt][0] = f2tf(As[r * 36 + ks + lc4]);
                af[mt][1] = f2tf(As[(r + 8) * 36 + ks + lc4]);
                af[mt][2] = f2tf(As[r * 36 + ks + lc4 + 4]);
                af[mt][3] = f2tf(As[(r + 8) * 36 + ks + lc4 + 4]);
            }
            #pragma unroll
            for (int nt = 0; nt < 8; nt++) {
                int n = wn + nt * 8 + lr;
                bf[nt][0] = f2tf(Bs[n * 36 + ks + lc4]);
                bf[nt][1] = f2tf(Bs[n * 36 + ks + lc4 + 4]);
            }
            #pragma unroll
            for (int mt = 0; mt < 2; mt++)
                #pragma unroll
                for (int nt = 0; nt < 8; nt++)
                    mma_tf32(acc[mt * 8 + nt], af[mt], bf[nt], acc[mt * 8 + nt]);
        }
        __syncthreads();
    }

    #pragma unroll
    for (int mt = 0; mt < 2; mt++)
        #pragma unroll
        for (int nt = 0; nt < 8; nt++) {
            int n = n0 + wn + nt * 8 + (lc4 << 1);
            int h = n >> 5, c = n & 31;
            #pragma unroll
            for (int hf = 0; hf < 2; hf++) {
                int r = r0 + wm + mt * 16 + lr + hf * 8;
                int l = r >> 8, s = r & 255;
                float v0 = acc[mt * 8 + nt][hf * 2 + 0];
                float v1 = acc[mt * 8 + nt][hf * 2 + 1];
                if (mat == 0) {
                    v0 *= 0.17677669529663687f;
                    v1 *= 0.17677669529663687f;
                } else if (mat == 3) {
                    v0 = 1.0f / (1.0f + __expf(-(v0 + bgv[n])));
                    v1 = 1.0f / (1.0f + __expf(-(v1 + bgv[n + 1])));
                }
                float* dst = g_P + (size_t)mat * SEG
                           + ((size_t)((l * HN + h) * SDIM + s)) * CN + c;
                *(float2*)dst = make_float2(v0, v1);
            }
        }
}

// ============================================================
// Attention (tf32 mma, flash-style): 1 block per (l,h), 8 warps,
// warp = 32 query rows, key chunks of 64, online softmax.
// Smem: K[256][36] V[256][40] P[8][32][68] bias[256] = 148480 B
// ============================================================
#define ATTN_SMEM_FLOATS (256*36 + 256*40 + 8*32*68 + 256)

__global__ __launch_bounds__(256) void attn_mma_kernel() {
    extern __shared__ float sm[];
    float* Ks = sm;
    float* Vs = sm + 256 * 36;
    float* Ps = Vs + 256 * 40;
    float* Bb = Ps + 8 * 32 * 68;

    int lh = blockIdx.x;
    int l = lh >> 3, h = lh & 7;
    size_t base = (size_t)lh * SDIM * CN;
    const float* Qg = g_P + base;
    const float* Kg = g_P + SEG + base;
    const float* Vg = g_P + 2 * SEG + base;
    const float* Gg = g_P + 3 * SEG + base;

    int tid = threadIdx.x, warp = tid >> 5, lane = tid & 31;
    int lr = lane >> 2, lc4 = lane & 3;

    #pragma unroll
    for (int i = 0; i < 8; i++) {
        int idx = tid + (i << 8);
        int t = idx >> 3, c4 = (idx & 7) << 2;
        float4 kv = *(const float4*)(Kg + t * 32 + c4);
        *(float4*)&Ks[t * 36 + c4] = kv;
        float4 vv = *(const float4*)(Vg + t * 32 + c4);
        *(float4*)&Vs[t * 40 + c4] = vv;
    }
    Bb[tid] = g_bias[l * SDIM + tid];
    __syncthreads();

    int qb = warp << 5;
    // Q fragments (A layout), kept in registers for all chunks
    unsigned qf[4][2][4];
    #pragma unroll
    for (int ks = 0; ks < 4; ks++)
        #pragma unroll
        for (int mt = 0; mt < 2; mt++) {
            int r = qb + mt * 16 + lr;
            int c = ks * 8 + lc4;
            qf[ks][mt][0] = f2tf(Qg[r * 32 + c]);
            qf[ks][mt][1] = f2tf(Qg[(r + 8) * 32 + c]);
            qf[ks][mt][2] = f2tf(Qg[r * 32 + c + 4]);
            qf[ks][mt][3] = f2tf(Qg[(r + 8) * 32 + c + 4]);
        }

    float mrow[2][2] = {{-3.0e38f, -3.0e38f}, {-3.0e38f, -3.0e38f}};
    float srow[2][2] = {};
    float ctx[2][4][4] = {};
    float* Pw = Ps + warp * 32 * 68;

    for (int t0 = 0; t0 < 256; t0 += 64) {
        // ---- logits chunk 32x64 via QK^T ----
        float lg[2][8][4] = {};
        #pragma unroll
        for (int ks = 0; ks < 4; ks++) {
            unsigned bf[8][2];
            #pragma unroll
            for (int nt = 0; nt < 8; nt++) {
                int kt = t0 + nt * 8 + lr;
                bf[nt][0] = f2tf(Ks[kt * 36 + ks * 8 + lc4]);
                bf[nt][1] = f2tf(Ks[kt * 36 + ks * 8 + lc4 + 4]);
            }
            #pragma unroll
            for (int mt = 0; mt < 2; mt++)
                #pragma unroll
                for (int nt = 0; nt < 8; nt++)
                    mma_tf32(lg[mt][nt], qf[ks][mt], bf[nt], lg[mt][nt]);
        }
        // ---- bias + chunk max ----
        float cmax[2][2] = {{-3.0e38f, -3.0e38f}, {-3.0e38f, -3.0e38f}};
        #pragma unroll
        for (int mt = 0; mt < 2; mt++)
            #pragma unroll
            for (int nt = 0; nt < 8; nt++) {
                float b0 = Bb[t0 + nt * 8 + (lc4 << 1)];
                float b1 = Bb[t0 + nt * 8 + (lc4 << 1) + 1];
                lg[mt][nt][0] += b0; lg[mt][nt][1] += b1;
                lg[mt][nt][2] += b0; lg[mt][nt][3] += b1;
                cmax[mt][0] = fmaxf(cmax[mt][0], fmaxf(lg[mt][nt][0], lg[mt][nt][1]));
                cmax[mt][1] = fmaxf(cmax[mt][1], fmaxf(lg[mt][nt][2], lg[mt][nt][3]));
            }
        float corr[2][2], csum[2][2] = {};
        #pragma unroll
        for (int mt = 0; mt < 2; mt++)
            #pragma unroll
            for (int hf = 0; hf < 2; hf++) {
                float v = cmax[mt][hf];
                v = fmaxf(v, __shfl_xor_sync(0xFFFFFFFFu, v, 1));
                v = fmaxf(v, __shfl_xor_sync(0xFFFFFFFFu, v, 2));
                float nm = fmaxf(mrow[mt][hf], v);
                corr[mt][hf] = __expf(mrow[mt][hf] - nm);
                mrow[mt][hf] = nm;
            }
        // ---- exp, stage P, partial sums ----
        #pragma unroll
        for (int mt = 0; mt < 2; mt++)
            #pragma unroll
            for (int nt = 0; nt < 8; nt++) {
                float p0 = __expf(lg[mt][nt][0] - mrow[mt][0]);
                float p1 = __expf(lg[mt][nt][1] - mrow[mt][0]);
                float p2 = __expf(lg[mt][nt][2] - mrow[mt][1]);
                float p3 = __expf(lg[mt][nt][3] - mrow[mt][1]);
                csum[mt][0] += p0 + p1;
                csum[mt][1] += p2 + p3;
                int col = nt * 8 + (lc4 << 1);
                int r = mt * 16 + lr;
                *(float2*)&Pw[r * 68 + col] = make_float2(p0, p1);
                *(float2*)&Pw[(r + 8) * 68 + col] = make_float2(p2, p3);
            }
        #pragma unroll
        for (int mt = 0; mt < 2; mt++)
            #pragma unroll
            for (int hf = 0; hf < 2; hf++) {
                float v = csum[mt][hf];
                v += __shfl_xor_sync(0xFFFFFFFFu, v, 1);
                v += __shfl_xor_sync(0xFFFFFFFFu, v, 2);
                srow[mt][hf] = srow[mt][hf] * corr[mt][hf] + v;
            }
        // ---- rescale ctx, then ctx += P @ V ----
        #pragma unroll
        for (int mt = 0; mt < 2; mt++)
            #pragma unroll
            for (int ct = 0; ct < 4; ct++) {
                ctx[mt][ct][0] *= corr[mt][0];
                ctx[mt][ct][1] *= corr[mt][0];
                ctx[mt][ct][2] *= corr[mt][1];
                ctx[mt][ct][3] *= corr[mt][1];
            }
        __syncwarp();
        #pragma unroll
        for (int ks2 = 0; ks2 < 8; ks2++) {
            unsigned pa[2][4];
            #pragma unroll
            for (int mt = 0; mt < 2; mt++) {
                int r = mt * 16 + lr;
                int c = ks2 * 8 + lc4;
                pa[mt][0] = f2tf(Pw[r * 68 + c]);
                pa[mt][1] = f2tf(Pw[(r + 8) * 68 + c]);
                pa[mt][2] = f2tf(Pw[r * 68 + c + 4]);
                pa[mt][3] = f2tf(Pw[(r + 8) * 68 + c + 4]);
            }
            unsigned vb[4][2];
            #pragma unroll
            for (int ct = 0; ct < 4; ct++) {
                int key = t0 + ks2 * 8 + lc4;
                int c = ct * 8 + lr;
                vb[ct][0] = f2tf(Vs[key * 40 + c]);
                vb[ct][1] = f2tf(Vs[(key + 4) * 40 + c]);
            }
            #pragma unroll
            for (int mt = 0; mt < 2; mt++)
                #pragma unroll
                for (int ct = 0; ct < 4; ct++)
                    mma_tf32(ctx[mt][ct], pa[mt], vb[ct], ctx[mt][ct]);
        }
        __syncwarp();
    }

    // ---- normalize, gate, write ----
    float inv[2][2];
    #pragma unroll
    for (int mt = 0; mt < 2; mt++) {
        inv[mt][0] = 1.0f / srow[mt][0];
        inv[mt][1] = 1.0f / srow[mt][1];
    }
    #pragma unroll
    for (int mt = 0; mt < 2; mt++)
        #pragma unroll
        for (int ct = 0; ct < 4; ct++) {
            int c = ct * 8 + (lc4 << 1);
            #pragma unroll
            for (int hf = 0; hf < 2; hf++) {
                int s = qb + mt * 16 + lr + hf * 8;
                float2 g2 = *(const float2*)(Gg + s * 32 + c);
                float2 o;
                o.x = ctx[mt][ct][hf * 2 + 0] * inv[mt][hf] * g2.x;
                o.y = ctx[mt][ct][hf * 2 + 1] * inv[mt][hf] * g2.y;
                *(float2*)(g_CTX + ((size_t)(l * SDIM + s)) * DDIM + h * CN + c) = o;
            }
        }
}

// ============================================================
// Output GEMM (tf32 mma): same scheme as proj, writes transposed out.
// ============================================================
__global__ __launch_bounds__(256, 2) void out_mma_kernel(
    const float* __restrict__ wo, const float* __restrict__ bo,
    float* __restrict__ out) {
    __shared__ float As[128 * 36];
    __shared__ float Bs[128 * 36];

    int tid = threadIdx.x, warp = tid >> 5, lane = tid & 31;
    int lr = lane >> 2, lc4 = lane & 3;
    int wm = (warp >> 1) << 5;
    int wn = (warp & 1) << 6;

    int r0 = blockIdx.x << 7;
    int n0 = blockIdx.y << 7;

    float acc[16][4] = {};

    for (int k0 = 0; k0 < 256; k0 += 32) {
        #pragma unroll
        for (int i = 0; i < 4; i++) {
            int idx = tid + (i << 8);
            int row = idx >> 3, c4 = (idx & 7) << 2;
            float4 v = *(const float4*)(g_CTX + (size_t)(r0 + row) * 256 + k0 + c4);
            *(float4*)&As[row * 36 + c4] = v;
            float4 b = *(const float4*)(wo + (size_t)(n0 + row) * 256 + k0 + c4);
            *(float4*)&Bs[row * 36 + c4] = b;
        }
        __syncthreads();
        #pragma unroll
        for (int ks = 0; ks < 32; ks += 8) {
            unsigned af[2][4], bf[8][2];
            #pragma unroll
            for (int mt = 0; mt < 2; mt++) {
                int r = wm + mt * 16 + lr;
                af[mt][0] = f2tf(As[r * 36 + ks + lc4]);
                af[mt][1] = f2tf(As[(r + 8) * 36 + ks + lc4]);
                af[mt][2] = f2tf(As[r * 36 + ks + lc4 + 4]);
                af[mt][3] = f2tf(As[(r + 8) * 36 + ks + lc4 + 4]);
            }
            #pragma unroll
            for (int nt = 0; nt < 8; nt++) {
                int n = wn + nt * 8 + lr;
                bf[nt][0] = f2tf(Bs[n * 36 + ks + lc4]);
                bf[nt][1] = f2tf(Bs[n * 36 + ks + lc4 + 4]);
            }
            #pragma unroll
            for (int mt = 0; mt < 2; mt++)
                #pragma unroll
                for (int nt = 0; nt < 8; nt++)
                    mma_tf32(acc[mt * 8 + nt], af[mt], bf[nt], acc[mt * 8 + nt]);
        }
        __syncthreads();
    }

    #pragma unroll
    for (int mt = 0; mt < 2; mt++)
        #pragma unroll
        for (int nt = 0; nt < 8; nt++) {
            int n = n0 + wn + nt * 8 + (lc4 << 1);
            #pragma unroll
            for (int hf = 0; hf < 2; hf++) {
                int r = r0 + wm + mt * 16 + lr + hf * 8;
                int l = r >> 8, s = r & 255;
                float2 o;
                o.x = acc[mt * 8 + nt][hf * 2 + 0] + bo[n];
                o.y = acc[mt * 8 + nt][hf * 2 + 1] + bo[n + 1];
                *(float2*)(out + (size_t)(s * LDIM + l) * DDIM + n) = o;
            }
        }
}

// ============================================================
extern "C" void kernel_launch(void* const* d_in, const int* in_sizes, int n_in,
                              void* d_out, int out_size) {
    const float* m        = (const float*)d_in[0];
    const void*  seqp     = d_in[1];
    const void*  resp     = d_in[2];
    const float* ln_scale = (const float*)d_in[3];
    const float* ln_bias  = (const float*)d_in[4];
    const float* wq       = (const float*)d_in[5];
    const float* wk       = (const float*)d_in[6];
    const float* wv       = (const float*)d_in[7];
    const float* wg       = (const float*)d_in[8];
    const float* bg       = (const float*)d_in[9];
    const float* wo       = (const float*)d_in[10];
    const float* bo       = (const float*)d_in[11];
    float* out = (float*)d_out;

    const int attn_smem = ATTN_SMEM_FLOATS * (int)sizeof(float); // 148480 B
    cudaFuncSetAttribute(attn_mma_kernel,
                         cudaFuncAttributeMaxDynamicSharedMemorySize, attn_smem);

    mask_kernel<<<LDIM, 256>>>(seqp, resp);
    ln_kernel<<<NROWS, 256>>>(m, ln_scale, ln_bias);
    proj_mma_kernel<<<dim3(NROWS / 128, 8), 256>>>(wq, wk, wv, wg, bg);
    attn_mma_kernel<<<LDIM * HN, 256, attn_smem>>>();
    out_mma_kernel<<<dim3(NROWS / 128, 2), 256>>>(wo, bo, out);
}

// round 4
// speedup vs baseline: 3.1366x; 1.2367x over previous
#include <cuda_runtime.h>
#include <cstdint>
#include <cstddef>

#define SDIM 256
#define LDIM 192
#define DDIM 256
#define HN   8
#define CN   32
#define NROWS (LDIM*SDIM)
#define SEG  ((size_t)NROWS*DDIM)

__device__ float g_XN[(size_t)NROWS*DDIM];
__device__ float g_P[(size_t)4*NROWS*DDIM];
__device__ float g_CTX[(size_t)NROWS*DDIM];
__device__ float g_bias[LDIM*SDIM];

// ---------- tf32 helpers ----------
__device__ __forceinline__ unsigned f2tf(float f) {
    unsigned u;
    asm("cvt.rna.tf32.f32 %0, %1;" : "=r"(u) : "f"(f));
    return u;
}
__device__ __forceinline__ float f2tff(float f) {   // tf32 pattern as float
    return __uint_as_float(f2tf(f));
}
__device__ __forceinline__ void mma_tf32(float* d, const unsigned* a,
                                         const unsigned* b, const float* c) {
    asm("mma.sync.aligned.m16n8k8.row.col.f32.tf32.tf32.f32 "
        "{%0,%1,%2,%3}, {%4,%5,%6,%7}, {%8,%9}, {%10,%11,%12,%13};"
        : "=f"(d[0]), "=f"(d[1]), "=f"(d[2]), "=f"(d[3])
        : "r"(a[0]), "r"(a[1]), "r"(a[2]), "r"(a[3]),
          "r"(b[0]), "r"(b[1]),
          "f"(c[0]), "f"(c[1]), "f"(c[2]), "f"(c[3]));
}

// ============================================================
// Pad mask (runtime dtype classification for bool inputs)
// ============================================================
__device__ __forceinline__ int classify_words(const int* w, int nwords) {
    int wordlike = 1;
    for (int i = 0; i < nwords; i++) {
        int v = w[i];
        if (v != 0 && v != 1 && v != 0x3F800000) wordlike = 0;
    }
    return wordlike;
}

__global__ void mask_kernel(const void* __restrict__ seqp,
                            const void* __restrict__ resp) {
    __shared__ int s_seqw, s_resw;
    if (threadIdx.x == 0) {
        s_seqw = classify_words((const int*)seqp, 64);
        s_resw = classify_words((const int*)resp, 48);
    }
    __syncthreads();
    const int seqw = s_seqw, resw = s_resw;
    int idx = blockIdx.x * 256 + threadIdx.x;
    int l = idx >> 8;
    int t = idx & 255;
    int rp = resw ? (((const int*)resp)[l] != 0)
                  : (((const unsigned char*)resp)[l] != 0);
    int sp = seqw ? (((const int*)seqp)[t] != 0)
                  : (((const unsigned char*)seqp)[t] != 0);
    g_bias[idx] = (rp | sp) ? -10000.0f : 0.0f;
}

// ============================================================
// LayerNorm (transpose on the fly)
// ============================================================
__global__ __launch_bounds__(256) void ln_kernel(const float* __restrict__ m,
                                                 const float* __restrict__ scale,
                                                 const float* __restrict__ bias) {
    int r = blockIdx.x;
    int l = r >> 8;
    int s = r & 255;
    int d = threadIdx.x;
    float v = m[((size_t)(s * LDIM + l)) * DDIM + d];

    float sum = v, sq = v * v;
    #pragma unroll
    for (int o = 16; o > 0; o >>= 1) {
        sum += __shfl_xor_sync(0xFFFFFFFFu, sum, o);
        sq  += __shfl_xor_sync(0xFFFFFFFFu, sq, o);
    }
    __shared__ float ssum[8], ssq[8];
    int w = threadIdx.x >> 5, ln = threadIdx.x & 31;
    if (ln == 0) { ssum[w] = sum; ssq[w] = sq; }
    __syncthreads();
    if (w == 0) {
        float a = (ln < 8) ? ssum[ln] : 0.f;
        float b = (ln < 8) ? ssq[ln]  : 0.f;
        #pragma unroll
        for (int o = 4; o > 0; o >>= 1) {
            a += __shfl_xor_sync(0xFFFFFFFFu, a, o);
            b += __shfl_xor_sync(0xFFFFFFFFu, b, o);
        }
        if (ln == 0) { ssum[0] = a; ssq[0] = b; }
    }
    __syncthreads();
    float mu   = ssum[0] * (1.0f / DDIM);
    float var  = ssq[0] * (1.0f / DDIM) - mu * mu;
    float rstd = rsqrtf(var + 1e-5f);
    g_XN[(size_t)r * DDIM + d] = (v - mu) * rstd * scale[d] + bias[d];
}

// ============================================================
// Projection GEMM (tf32 mma): block 128x128, 8 warps (4m x 2n).
// Register-prefetched K tiles; tf32 pre-converted at staging.
// ============================================================
__global__ __launch_bounds__(256, 2) void proj_mma_kernel(
    const float* __restrict__ wq, const float* __restrict__ wk,
    const float* __restrict__ wv, const float* __restrict__ wg,
    const float* __restrict__ bgv) {
    __shared__ float As[128 * 36];
    __shared__ float Bs[128 * 36];

    int tid = threadIdx.x, warp = tid >> 5, lane = tid & 31;
    int lr = lane >> 2, lc4 = lane & 3;
    int wm = (warp >> 1) << 5;
    int wn = (warp & 1) << 6;

    int r0  = blockIdx.x << 7;
    int mat = blockIdx.y >> 1;
    int n0  = (blockIdx.y & 1) << 7;
    const float* W = (mat == 0) ? wq : (mat == 1) ? wk : (mat == 2) ? wv : wg;
    const float* Ag = g_XN;

    int srow = tid >> 3, sc4 = (tid & 7) << 2;   // staging row / col4
    const float* Aip = Ag + (size_t)(r0 + srow) * 256 + sc4;
    const float* Bip = W  + (size_t)(n0 + srow) * 256 + sc4;

    float acc[16][4] = {};
    float4 pa_[4], pb_[4];
    #pragma unroll
    for (int i = 0; i < 4; i++) {
        pa_[i] = *(const float4*)(Aip + (size_t)i * 32 * 256);
        pb_[i] = *(const float4*)(Bip + (size_t)i * 32 * 256);
    }

    for (int t = 0; t < 8; t++) {
        __syncthreads();
        #pragma unroll
        for (int i = 0; i < 4; i++) {
            int row = srow + i * 32;
            float* a = &As[row * 36 + sc4];
            a[0] = f2tff(pa_[i].x); a[1] = f2tff(pa_[i].y);
            a[2] = f2tff(pa_[i].z); a[3] = f2tff(pa_[i].w);
            float* b = &Bs[row * 36 + sc4];
            b[0] = f2tff(pb_[i].x); b[1] = f2tff(pb_[i].y);
            b[2] = f2tff(pb_[i].z); b[3] = f2tff(pb_[i].w);
        }
        __syncthreads();
        if (t < 7) {
            int k0 = (t + 1) * 32;
            #pragma unroll
            for (int i = 0; i < 4; i++) {
                pa_[i] = *(const float4*)(Aip + (size_t)i * 32 * 256 + k0);
                pb_[i] = *(const float4*)(Bip + (size_t)i * 32 * 256 + k0);
            }
        }
        #pragma unroll
        for (int ks = 0; ks < 32; ks += 8) {
            unsigned af[2][4], bf[8][2];
            #pragma unroll
            for (int mt = 0; mt < 2; mt++) {
                int r = wm + mt * 16 + lr;
                af[mt][0] = __float_as_uint(As[r * 36 + ks + lc4]);
                af[mt][1] = __float_as_uint(As[(r + 8) * 36 + ks + lc4]);
                af[mt][2] = __float_as_uint(As[r * 36 + ks + lc4 + 4]);
                af[mt][3] = __float_as_uint(As[(r + 8) * 36 + ks + lc4 + 4]);
            }
            #pragma unroll
            for (int nt = 0; nt < 8; nt++) {
                int n = wn + nt * 8 + lr;
                bf[nt][0] = __float_as_uint(Bs[n * 36 + ks + lc4]);
                bf[nt][1] = __float_as_uint(Bs[n * 36 + ks + lc4 + 4]);
            }
            #pragma unroll
            for (int mt = 0; mt < 2; mt++)
                #pragma unroll
                for (int nt = 0; nt < 8; nt++)
                    mma_tf32(acc[mt * 8 + nt], af[mt], bf[nt], acc[mt * 8 + nt]);
        }
    }

    #pragma unroll
    for (int mt = 0; mt < 2; mt++)
        #pragma unroll
        for (int nt = 0; nt < 8; nt++) {
            int n = n0 + wn + nt * 8 + (lc4 << 1);
            int h = n >> 5, c = n & 31;
            #pragma unroll
            for (int hf = 0; hf < 2; hf++) {
                int r = r0 + wm + mt * 16 + lr + hf * 8;
                int l = r >> 8, s = r & 255;
                float v0 = acc[mt * 8 + nt][hf * 2 + 0];
                float v1 = acc[mt * 8 + nt][hf * 2 + 1];
                if (mat == 0) {
                    v0 *= 0.17677669529663687f;
                    v1 *= 0.17677669529663687f;
                } else if (mat == 3) {
                    v0 = 1.0f / (1.0f + __expf(-(v0 + bgv[n])));
                    v1 = 1.0f / (1.0f + __expf(-(v1 + bgv[n + 1])));
                }
                float* dst = g_P + (size_t)mat * SEG
                           + ((size_t)((l * HN + h) * SDIM + s)) * CN + c;
                *(float2*)dst = make_float2(v0, v1);
            }
        }
}

// ============================================================
// Attention v2: 2 blocks per (l,h) (128 queries each), 8 warps,
// warp = 16 query rows. K/V pre-converted tf32 in smem; P re-laid
// out fragment-wise through a 640B/warp smem buffer.
// Smem: K[256][36] V[256][40] bias[256] P[8][160] = 83968 B -> 2 CTA/SM
// ============================================================
#define ATTN_SMEM_FLOATS (256*36 + 256*40 + 256 + 8*160)

__global__ __launch_bounds__(256, 2) void attn_mma_kernel() {
    extern __shared__ float sm[];
    float* Ks = sm;
    float* Vs = Ks + 256 * 36;
    float* Bb = Vs + 256 * 40;
    float* Pst = Bb + 256;

    int bid = blockIdx.x;
    int lh = bid >> 1;
    int qhalf = bid & 1;
    int l = lh >> 3, h = lh & 7;
    size_t base = (size_t)lh * SDIM * CN;
    const float* Qg = g_P + base;
    const float* Kg = g_P + SEG + base;
    const float* Vg = g_P + 2 * SEG + base;
    const float* Gg = g_P + 3 * SEG + base;

    int tid = threadIdx.x, warp = tid >> 5, lane = tid & 31;
    int lr = lane >> 2, lc4 = lane & 3;

    #pragma unroll
    for (int i = 0; i < 8; i++) {
        int idx = tid + (i << 8);
        int t = idx >> 3, c4 = (idx & 7) << 2;
        float4 kv = *(const float4*)(Kg + t * 32 + c4);
        float* kd = &Ks[t * 36 + c4];
        kd[0] = f2tff(kv.x); kd[1] = f2tff(kv.y);
        kd[2] = f2tff(kv.z); kd[3] = f2tff(kv.w);
        float4 vv = *(const float4*)(Vg + t * 32 + c4);
        float* vd = &Vs[t * 40 + c4];
        vd[0] = f2tff(vv.x); vd[1] = f2tff(vv.y);
        vd[2] = f2tff(vv.z); vd[3] = f2tff(vv.w);
    }
    Bb[tid] = g_bias[l * SDIM + tid];
    __syncthreads();

    int qb = qhalf * 128 + warp * 16;
    unsigned qf[4][4];
    #pragma unroll
    for (int ks = 0; ks < 4; ks++) {
        int c = ks * 8 + lc4;
        qf[ks][0] = f2tf(Qg[(qb + lr) * 32 + c]);
        qf[ks][1] = f2tf(Qg[(qb + lr + 8) * 32 + c]);
        qf[ks][2] = f2tf(Qg[(qb + lr) * 32 + c + 4]);
        qf[ks][3] = f2tf(Qg[(qb + lr + 8) * 32 + c + 4]);
    }

    float mrow[2] = {-3.0e38f, -3.0e38f};
    float srow[2] = {0.f, 0.f};
    float ctx[4][4] = {};
    float* Pw = Pst + warp * 160;

    for (int t0 = 0; t0 < 256; t0 += 64) {
        // ---- logits 16x64 ----
        float lg[8][4] = {};
        #pragma unroll
        for (int ks = 0; ks < 4; ks++) {
            unsigned bf[8][2];
            #pragma unroll
            for (int nt = 0; nt < 8; nt++) {
                int kt = t0 + nt * 8 + lr;
                bf[nt][0] = __float_as_uint(Ks[kt * 36 + ks * 8 + lc4]);
                bf[nt][1] = __float_as_uint(Ks[kt * 36 + ks * 8 + lc4 + 4]);
            }
            #pragma unroll
            for (int nt = 0; nt < 8; nt++)
                mma_tf32(lg[nt], qf[ks], bf[nt], lg[nt]);
        }
        // ---- bias + chunk max ----
        float cmax[2] = {-3.0e38f, -3.0e38f};
        #pragma unroll
        for (int nt = 0; nt < 8; nt++) {
            float b0 = Bb[t0 + nt * 8 + (lc4 << 1)];
            float b1 = Bb[t0 + nt * 8 + (lc4 << 1) + 1];
            lg[nt][0] += b0; lg[nt][1] += b1;
            lg[nt][2] += b0; lg[nt][3] += b1;
            cmax[0] = fmaxf(cmax[0], fmaxf(lg[nt][0], lg[nt][1]));
            cmax[1] = fmaxf(cmax[1], fmaxf(lg[nt][2], lg[nt][3]));
        }
        float corr[2];
        #pragma unroll
        for (int hf = 0; hf < 2; hf++) {
            float v = cmax[hf];
            v = fmaxf(v, __shfl_xor_sync(0xFFFFFFFFu, v, 1));
            v = fmaxf(v, __shfl_xor_sync(0xFFFFFFFFu, v, 2));
            float nm = fmaxf(mrow[hf], v);
            corr[hf] = __expf(mrow[hf] - nm);
            mrow[hf] = nm;
        }
        // ---- exp (tf32-round for PV), partial sums ----
        float csum[2] = {0.f, 0.f};
        #pragma unroll
        for (int nt = 0; nt < 8; nt++) {
            float p0 = __expf(lg[nt][0] - mrow[0]);
            float p1 = __expf(lg[nt][1] - mrow[0]);
            float p2 = __expf(lg[nt][2] - mrow[1]);
            float p3 = __expf(lg[nt][3] - mrow[1]);
            csum[0] += p0 + p1;
            csum[1] += p2 + p3;
            lg[nt][0] = f2tff(p0); lg[nt][1] = f2tff(p1);
            lg[nt][2] = f2tff(p2); lg[nt][3] = f2tff(p3);
        }
        #pragma unroll
        for (int hf = 0; hf < 2; hf++) {
            float v = csum[hf];
            v += __shfl_xor_sync(0xFFFFFFFFu, v, 1);
            v += __shfl_xor_sync(0xFFFFFFFFu, v, 2);
            srow[hf] = srow[hf] * corr[hf] + v;
        }
        #pragma unroll
        for (int ct = 0; ct < 4; ct++) {
            ctx[ct][0] *= corr[0];
            ctx[ct][1] *= corr[0];
            ctx[ct][2] *= corr[1];
            ctx[ct][3] *= corr[1];
        }
        // ---- PV: re-layout each 16x8 P fragment via smem, then mma ----
        #pragma unroll
        for (int ks2 = 0; ks2 < 8; ks2++) {
            *(float2*)&Pw[lr * 10 + (lc4 << 1)] =
                make_float2(lg[ks2][0], lg[ks2][1]);
            *(float2*)&Pw[(lr + 8) * 10 + (lc4 << 1)] =
                make_float2(lg[ks2][2], lg[ks2][3]);
            __syncwarp();
            unsigned pa[4];
            pa[0] = __float_as_uint(Pw[lr * 10 + lc4]);
            pa[1] = __float_as_uint(Pw[(lr + 8) * 10 + lc4]);
            pa[2] = __float_as_uint(Pw[lr * 10 + lc4 + 4]);
            pa[3] = __float_as_uint(Pw[(lr + 8) * 10 + lc4 + 4]);
            int key = t0 + ks2 * 8 + lc4;
            unsigned vb[4][2];
            #pragma unroll
            for (int ct = 0; ct < 4; ct++) {
                int c = ct * 8 + lr;
                vb[ct][0] = __float_as_uint(Vs[key * 40 + c]);
                vb[ct][1] = __float_as_uint(Vs[(key + 4) * 40 + c]);
            }
            #pragma unroll
            for (int ct = 0; ct < 4; ct++)
                mma_tf32(ctx[ct], pa, vb[ct], ctx[ct]);
            __syncwarp();
        }
    }

    // ---- normalize, gate, write ----
    float inv0 = 1.0f / srow[0];
    float inv1 = 1.0f / srow[1];
    #pragma unroll
    for (int ct = 0; ct < 4; ct++) {
        int c = ct * 8 + (lc4 << 1);
        int s0 = qb + lr;
        float2 g0 = *(const float2*)(Gg + s0 * 32 + c);
        float2 o0;
        o0.x = ctx[ct][0] * inv0 * g0.x;
        o0.y = ctx[ct][1] * inv0 * g0.y;
        *(float2*)(g_CTX + ((size_t)(l * SDIM + s0)) * DDIM + h * CN + c) = o0;
        int s1 = s0 + 8;
        float2 g1 = *(const float2*)(Gg + s1 * 32 + c);
        float2 o1;
        o1.x = ctx[ct][2] * inv1 * g1.x;
        o1.y = ctx[ct][3] * inv1 * g1.y;
        *(float2*)(g_CTX + ((size_t)(l * SDIM + s1)) * DDIM + h * CN + c) = o1;
    }
}

// ============================================================
// Output GEMM (tf32 mma) with prefetch + pre-converted staging.
// ============================================================
__global__ __launch_bounds__(256, 2) void out_mma_kernel(
    const float* __restrict__ wo, const float* __restrict__ bo,
    float* __restrict__ out) {
    __shared__ float As[128 * 36];
    __shared__ float Bs[128 * 36];

    int tid = threadIdx.x, warp = tid >> 5, lane = tid & 31;
    int lr = lane >> 2, lc4 = lane & 3;
    int wm = (warp >> 1) << 5;
    int wn = (warp & 1) << 6;

    int r0 = blockIdx.x << 7;
    int n0 = blockIdx.y << 7;

    int srow = tid >> 3, sc4 = (tid & 7) << 2;
    const float* Aip = g_CTX + (size_t)(r0 + srow) * 256 + sc4;
    const float* Bip = wo    + (size_t)(n0 + srow) * 256 + sc4;

    float acc[16][4] = {};
    float4 pa_[4], pb_[4];
    #pragma unroll
    for (int i = 0; i < 4; i++) {
        pa_[i] = *(const float4*)(Aip + (size_t)i * 32 * 256);
        pb_[i] = *(const float4*)(Bip + (size_t)i * 32 * 256);
    }

    for (int t = 0; t < 8; t++) {
        __syncthreads();
        #pragma unroll
        for (int i = 0; i < 4; i++) {
            int row = srow + i * 32;
            float* a = &As[row * 36 + sc4];
            a[0] = f2tff(pa_[i].x); a[1] = f2tff(pa_[i].y);
            a[2] = f2tff(pa_[i].z); a[3] = f2tff(pa_[i].w);
            float* b = &Bs[row * 36 + sc4];
            b[0] = f2tff(pb_[i].x); b[1] = f2tff(pb_[i].y);
            b[2] = f2tff(pb_[i].z); b[3] = f2tff(pb_[i].w);
        }
        __syncthreads();
        if (t < 7) {
            int k0 = (t + 1) * 32;
            #pragma unroll
            for (int i = 0; i < 4; i++) {
                pa_[i] = *(const float4*)(Aip + (size_t)i * 32 * 256 + k0);
                pb_[i] = *(const float4*)(Bip + (size_t)i * 32 * 256 + k0);
            }
        }
        #pragma unroll
        for (int ks = 0; ks < 32; ks += 8) {
            unsigned af[2][4], bf[8][2];
            #pragma unroll
            for (int mt = 0; mt < 2; mt++) {
                int r = wm + mt * 16 + lr;
                af[mt][0] = __float_as_uint(As[r * 36 + ks + lc4]);
                af[mt][1] = __float_as_uint(As[(r + 8) * 36 + ks + lc4]);
                af[mt][2] = __float_as_uint(As[r * 36 + ks + lc4 + 4]);
                af[mt][3] = __float_as_uint(As[(r + 8) * 36 + ks + lc4 + 4]);
            }
            #pragma unroll
            for (int nt = 0; nt < 8; nt++) {
                int n = wn + nt * 8 + lr;
                bf[nt][0] = __float_as_uint(Bs[n * 36 + ks + lc4]);
                bf[nt][1] = __float_as_uint(Bs[n * 36 + ks + lc4 + 4]);
            }
            #pragma unroll
            for (int mt = 0; mt < 2; mt++)
                #pragma unroll
                for (int nt = 0; nt < 8; nt++)
                    mma_tf32(acc[mt * 8 + nt], af[mt], bf[nt], acc[mt * 8 + nt]);
        }
    }

    #pragma unroll
    for (int mt = 0; mt < 2; mt++)
        #pragma unroll
        for (int nt = 0; nt < 8; nt++) {
            int n = n0 + wn + nt * 8 + (lc4 << 1);
            #pragma unroll
            for (int hf = 0; hf < 2; hf++) {
                int r = r0 + wm + mt * 16 + lr + hf * 8;
                int l = r >> 8, s = r & 255;
                float2 o;
                o.x = acc[mt * 8 + nt][hf * 2 + 0] + bo[n];
                o.y = acc[mt * 8 + nt][hf * 2 + 1] + bo[n + 1];
                *(float2*)(out + (size_t)(s * LDIM + l) * DDIM + n) = o;
            }
        }
}

// ============================================================
extern "C" void kernel_launch(void* const* d_in, const int* in_sizes, int n_in,
                              void* d_out, int out_size) {
    const float* m        = (const float*)d_in[0];
    const void*  seqp     = d_in[1];
    const void*  resp     = d_in[2];
    const float* ln_scale = (const float*)d_in[3];
    const float* ln_bias  = (const float*)d_in[4];
    const float* wq       = (const float*)d_in[5];
    const float* wk       = (const float*)d_in[6];
    const float* wv       = (const float*)d_in[7];
    const float* wg       = (const float*)d_in[8];
    const float* bg       = (const float*)d_in[9];
    const float* wo       = (const float*)d_in[10];
    const float* bo       = (const float*)d_in[11];
    float* out = (float*)d_out;

    const int attn_smem = ATTN_SMEM_FLOATS * (int)sizeof(float); // 83968 B
    cudaFuncSetAttribute(attn_mma_kernel,
                         cudaFuncAttributeMaxDynamicSharedMemorySize, attn_smem);

    mask_kernel<<<LDIM, 256>>>(seqp, resp);
    ln_kernel<<<NROWS, 256>>>(m, ln_scale, ln_bias);
    proj_mma_kernel<<<dim3(NROWS / 128, 8), 256>>>(wq, wk, wv, wg, bg);
    attn_mma_kernel<<<LDIM * HN * 2, 256, attn_smem>>>();
    out_mma_kernel<<<dim3(NROWS / 128, 2), 256>>>(wo, bo, out);
}